// round 5
// baseline (speedup 1.0000x reference)
#include <cuda_runtime.h>
#include <math.h>

#define SQ 2048
#define EM 512
#define NH 8
#define HD 64
#define EPSF 1e-15f

// ---------------- scratch (static device globals; no allocation) ----------------
__device__ float g_proj[3][SQ * EM];   // projected (then normalized) q/k/v points, [S][E]
__device__ float g_T[2][EM * SQ];      // q,k transposed to [E][S] for attention tile loads
__device__ float g_x2[3][SQ];          // per-token ||x||^2 of the raw inputs
__device__ float g_zn[3][EM];          // column norms of W
__device__ float g_chv[3][EM];         // cosh(2*r)
__device__ float g_shv[3][EM];         // sinh(2*r)
__device__ float g_pt2[3][NH * SQ];    // per-head ||point||^2 after normalization
__device__ float g_rinv[3][NH * SQ];   // 1/(1 - pt2)

// ---------------- kernel 1: W column norms + bias cosh/sinh ----------------
__global__ void colnorm_k(const float* __restrict__ W0, const float* __restrict__ W1,
                          const float* __restrict__ W2, const float* __restrict__ b0,
                          const float* __restrict__ b1, const float* __restrict__ b2) {
    int t = blockIdx.y;
    int j = blockIdx.x * blockDim.x + threadIdx.x;
    if (j >= EM) return;
    const float* W = (t == 0) ? W0 : ((t == 1) ? W1 : W2);
    const float* b = (t == 0) ? b0 : ((t == 1) ? b1 : b2);
    float s = 0.f;
    for (int i = 0; i < EM; i++) { float v = W[i * EM + j]; s = fmaf(v, v, s); }
    float zn = fmaxf(sqrtf(s), EPSF);
    float r2 = 2.f * b[j];
    g_zn[t][j] = zn;
    g_chv[t][j] = coshf(r2);
    g_shv[t][j] = sinhf(r2);
}

// ---------------- kernel 2: per-token input squared norms ----------------
__global__ void rownorm_k(const float* __restrict__ x0, const float* __restrict__ x1,
                          const float* __restrict__ x2) {
    int t = blockIdx.y, s = blockIdx.x, lane = threadIdx.x;
    const float* x = (t == 0) ? x0 : ((t == 1) ? x1 : x2);
    const float4* row = (const float4*)(x + (size_t)s * EM);
    float acc = 0.f;
    for (int i = lane; i < EM / 4; i += 32) {
        float4 v = row[i];
        acc += v.x * v.x + v.y * v.y + v.z * v.z + v.w * v.w;
    }
    #pragma unroll
    for (int m = 16; m; m >>= 1) acc += __shfl_xor_sync(0xffffffffu, acc, m);
    if (lane == 0) g_x2[t][s] = acc;
}

// ---------------- kernel 3: projection GEMM + h_linear epilogue ----------------
__global__ __launch_bounds__(256) void proj_k(
    const float* __restrict__ x0, const float* __restrict__ x1, const float* __restrict__ x2,
    const float* __restrict__ W0, const float* __restrict__ W1, const float* __restrict__ W2) {
    int t = blockIdx.z;
    const float* X = (t == 0) ? x0 : ((t == 1) ? x1 : x2);
    const float* W = (t == 0) ? W0 : ((t == 1) ? W1 : W2);
    int n0 = blockIdx.x * 64, m0 = blockIdx.y * 64;
    __shared__ float aT[16][68];
    __shared__ float bS[16][68];
    int tid = threadIdx.x;
    int tx = tid & 15, ty = tid >> 4;
    float acc[4][4] = {};
    for (int k0 = 0; k0 < EM; k0 += 16) {
        {
            int m = tid >> 2, kb = (tid & 3) * 4;
            float4 v = *(const float4*)(X + (size_t)(m0 + m) * EM + k0 + kb);
            aT[kb + 0][m] = v.x; aT[kb + 1][m] = v.y; aT[kb + 2][m] = v.z; aT[kb + 3][m] = v.w;
            int kk = tid >> 4, nb = (tid & 15) * 4;
            *(float4*)(&bS[kk][nb]) = *(const float4*)(W + (size_t)(k0 + kk) * EM + n0 + nb);
        }
        __syncthreads();
        #pragma unroll
        for (int kk = 0; kk < 16; kk++) {
            float4 a4 = *(const float4*)(&aT[kk][ty * 4]);
            float4 b4 = *(const float4*)(&bS[kk][tx * 4]);
            float av[4] = {a4.x, a4.y, a4.z, a4.w};
            float bv[4] = {b4.x, b4.y, b4.z, b4.w};
            #pragma unroll
            for (int j = 0; j < 4; j++)
                #pragma unroll
                for (int i = 0; i < 4; i++) acc[j][i] = fmaf(av[j], bv[i], acc[j][i]);
        }
        __syncthreads();
    }
    // epilogue: w = sinh(2*zn*asinh(inner*lam/zn*cosh(2r) - (lam-1)*sinh(2r)))
    int col_base = n0 + tx * 4;
    float znr[4], chr[4], shr[4];
    #pragma unroll
    for (int i = 0; i < 4; i++) {
        znr[i] = g_zn[t][col_base + i];
        chr[i] = g_chv[t][col_base + i];
        shr[i] = g_shv[t][col_base + i];
    }
    #pragma unroll
    for (int j = 0; j < 4; j++) {
        int row = m0 + ty * 4 + j;
        float x2 = g_x2[t][row];
        float lam = 2.f / (1.f - x2);
        #pragma unroll
        for (int i = 0; i < 4; i++) {
            float arg = (acc[j][i] * lam / znr[i]) * chr[i] - (lam - 1.f) * shr[i];
            float dd = 2.f * znr[i] * asinhf(arg);
            g_proj[t][(size_t)row * EM + col_base + i] = sinhf(dd);
        }
    }
}

// ---------------- kernel 4: ball normalization + per-head aux ----------------
__global__ void normaux_k() {
    int t = blockIdx.y, s = blockIdx.x, tid = threadIdx.x;  // 128 threads
    float* row = &g_proj[t][(size_t)s * EM];
    float4 v = ((float4*)row)[tid];
    float l4 = v.x * v.x + v.y * v.y + v.z * v.z + v.w * v.w;
    float tot = l4;
    #pragma unroll
    for (int m = 16; m; m >>= 1) tot += __shfl_xor_sync(0xffffffffu, tot, m);
    __shared__ float wsum[4];
    if ((tid & 31) == 0) wsum[tid >> 5] = tot;
    __syncthreads();
    float total = wsum[0] + wsum[1] + wsum[2] + wsum[3];
    float scale = 1.f / (1.f + sqrtf(1.f + total));
    v.x *= scale; v.y *= scale; v.z *= scale; v.w *= scale;
    ((float4*)row)[tid] = v;
    // per-head sumsq: head = tid/16 (16 threads x 4 cols = 64 cols)
    float hs = l4;
    #pragma unroll
    for (int m = 8; m; m >>= 1) hs += __shfl_xor_sync(0xffffffffu, hs, m);
    if ((tid & 15) == 0) {
        int h = tid >> 4;
        float pt2 = scale * scale * hs;
        g_pt2[t][h * SQ + s] = pt2;
        g_rinv[t][h * SQ + s] = 1.f / (1.f - pt2);
    }
}

// ---------------- kernel 5: transpose q,k to [E][S] ----------------
__global__ void transpose_k() {
    int t = blockIdx.z;  // 0:q 1:k
    __shared__ float tile[32][33];
    int c0 = blockIdx.x * 32, r0 = blockIdx.y * 32;
    int x = threadIdx.x, y = threadIdx.y;  // (32, 8)
    const float* src = g_proj[t];
    #pragma unroll
    for (int yy = y; yy < 32; yy += 8) tile[yy][x] = src[(size_t)(r0 + yy) * EM + c0 + x];
    __syncthreads();
    float* dst = g_T[t];
    #pragma unroll
    for (int yy = y; yy < 32; yy += 8) dst[(size_t)(c0 + yy) * SQ + r0 + x] = tile[x][yy];
}

// ---------------- kernel 6: causal hyperbolic attention + gyromidpoint ----------------
#define TPAD 68
#define ATTN_SMEM_FLOATS (4 * 64 * TPAD + 5 * 64)

__global__ __launch_bounds__(256) void attn_k(const float* __restrict__ stau,
                                              const float* __restrict__ sgam,
                                              float beta, float* __restrict__ out) {
    int bid = blockIdx.x;
    int h = bid & (NH - 1);
    int qt = (SQ / 64 - 1) - (bid >> 3);  // big q-tiles first for load balance
    int q0 = qt * 64;
    extern __shared__ float smem[];
    float* qT = smem;                 // [64 kk][TPAD]
    float* kT = qT + 64 * TPAD;       // [64 kk][TPAD]
    float* vS = kT + 64 * TPAD;       // [64 k ][TPAD]
    float* wS = vS + 64 * TPAD;       // [64 q ][TPAD]  (holds w*lamv)
    float* q2s = wS + 64 * TPAD;
    float* rqs = q2s + 64;
    float* k2s = rqs + 64;
    float* rks = k2s + 64;
    float* lvs = rks + 64;
    int tid = threadIdx.x, tx = tid & 15, ty = tid >> 4;
    float tau = __expf(stau[0]);
    float gamma = sgam[0];

    // load q tile (transposed layout: contiguous in token index)
    {
        int kk = tid >> 3, r8 = (tid & 7) * 8;
        const float* src = &g_T[0][(size_t)(h * HD) * SQ + q0];
        #pragma unroll
        for (int p = 0; p < 2; p++) {
            int K = kk + 32 * p;
            *(float4*)(&qT[K * TPAD + r8])     = *(const float4*)(src + (size_t)K * SQ + r8);
            *(float4*)(&qT[K * TPAD + r8 + 4]) = *(const float4*)(src + (size_t)K * SQ + r8 + 4);
        }
        if (tid < 64) {
            q2s[tid] = g_pt2[0][h * SQ + q0 + tid];
            rqs[tid] = g_rinv[0][h * SQ + q0 + tid];
        }
    }
    __syncthreads();
    float q2r[4], rqr[4];
    #pragma unroll
    for (int j = 0; j < 4; j++) { q2r[j] = q2s[ty * 4 + j]; rqr[j] = rqs[ty * 4 + j]; }

    float num[4][4] = {};
    float den[4] = {};

    for (int kt = 0; kt <= qt; kt++) {
        int k0 = kt * 64;
        {   // load k (transposed) + v (natural) tiles + per-key aux
            int kk = tid >> 3, r8 = (tid & 7) * 8;
            const float* ksrc = &g_T[1][(size_t)(h * HD) * SQ + k0];
            #pragma unroll
            for (int p = 0; p < 2; p++) {
                int K = kk + 32 * p;
                *(float4*)(&kT[K * TPAD + r8])     = *(const float4*)(ksrc + (size_t)K * SQ + r8);
                *(float4*)(&kT[K * TPAD + r8 + 4]) = *(const float4*)(ksrc + (size_t)K * SQ + r8 + 4);
            }
            const float* vsrc = &g_proj[2][(size_t)k0 * EM + h * HD];
            #pragma unroll
            for (int p = 0; p < 2; p++) {
                int R = (tid >> 3) + 32 * p;
                int c8 = (tid & 7) * 8;
                *(float4*)(&vS[R * TPAD + c8])     = *(const float4*)(vsrc + (size_t)R * EM + c8);
                *(float4*)(&vS[R * TPAD + c8 + 4]) = *(const float4*)(vsrc + (size_t)R * EM + c8 + 4);
            }
            if (tid < 64) {
                k2s[tid] = g_pt2[1][h * SQ + k0 + tid];
                rks[tid] = g_rinv[1][h * SQ + k0 + tid];
                lvs[tid] = 2.f * g_rinv[2][h * SQ + k0 + tid];
            }
        }
        __syncthreads();

        // phase 1: qk = Q.K^T over hd=64
        float qk[4][4] = {};
        #pragma unroll 8
        for (int kk = 0; kk < 64; kk++) {
            float4 a4 = *(const float4*)(&qT[kk * TPAD + ty * 4]);
            float4 b4 = *(const float4*)(&kT[kk * TPAD + tx * 4]);
            float av[4] = {a4.x, a4.y, a4.z, a4.w};
            float bv[4] = {b4.x, b4.y, b4.z, b4.w};
            #pragma unroll
            for (int j = 0; j < 4; j++)
                #pragma unroll
                for (int i = 0; i < 4; i++) qk[j][i] = fmaf(av[j], bv[i], qk[j][i]);
        }

        // per-key aux into regs
        float k2r[4], rkr[4], lvr[4];
        #pragma unroll
        for (int i = 0; i < 4; i++) {
            k2r[i] = k2s[tx * 4 + i]; rkr[i] = rks[tx * 4 + i]; lvr[i] = lvs[tx * 4 + i];
        }
        bool diag = (kt == qt);

        // transform: Poincare distance -> exp weight; stage w*lamv to smem
        #pragma unroll
        for (int j = 0; j < 4; j++) {
            int qg = q0 + ty * 4 + j;
            #pragma unroll
            for (int i = 0; i < 4; i++) {
                int kg = k0 + tx * 4 + i;
                float w;
                if (diag && kg > qg) {
                    w = 0.f;
                } else {
                    float d2 = fmaxf(q2r[j] + k2r[i] - 2.f * qk[j][i], 0.f);
                    float arg = fmaf(2.f * d2, rqr[j] * rkr[i], 1.f);
                    arg = fmaxf(arg, 1.f + 1e-7f);
                    float dist = __logf(arg + sqrtf((arg - 1.f) * (arg + 1.f)));
                    w = __expf(-tau * dist - gamma);
                }
                float wl = w * lvr[i];
                wS[(ty * 4 + j) * TPAD + tx * 4 + i] = wl;
                den[j] += wl - w;  // = w*(lamv-1)
            }
        }
        __syncthreads();

        // phase 2: num += W_l . V
        #pragma unroll 4
        for (int kk = 0; kk < 64; kk += 4) {
            float4 w0 = *(const float4*)(&wS[(ty * 4 + 0) * TPAD + kk]);
            float4 w1 = *(const float4*)(&wS[(ty * 4 + 1) * TPAD + kk]);
            float4 w2 = *(const float4*)(&wS[(ty * 4 + 2) * TPAD + kk]);
            float4 w3 = *(const float4*)(&wS[(ty * 4 + 3) * TPAD + kk]);
            float wa[4][4] = {{w0.x, w0.y, w0.z, w0.w}, {w1.x, w1.y, w1.z, w1.w},
                              {w2.x, w2.y, w2.z, w2.w}, {w3.x, w3.y, w3.z, w3.w}};
            #pragma unroll
            for (int c = 0; c < 4; c++) {
                float4 b4 = *(const float4*)(&vS[(kk + c) * TPAD + tx * 4]);
                float bb[4] = {b4.x, b4.y, b4.z, b4.w};
                #pragma unroll
                for (int j = 0; j < 4; j++)
                    #pragma unroll
                    for (int i = 0; i < 4; i++) num[j][i] = fmaf(wa[j][c], bb[i], num[j][i]);
            }
        }
        __syncthreads();
    }

    // epilogue: reduce den & ||g|| across the 16 tx lanes, Mobius half + beta-concat
    #pragma unroll
    for (int j = 0; j < 4; j++) {
        float d = den[j];
        #pragma unroll
        for (int m = 8; m; m >>= 1) d += __shfl_xor_sync(0xffffffffu, d, m);
        d = fmaxf(d, EPSF);
        float inv = 1.f / d;
        float g[4];
        float gs = 0.f;
        #pragma unroll
        for (int i = 0; i < 4; i++) { g[i] = num[j][i] * inv; gs += g[i] * g[i]; }
        #pragma unroll
        for (int m = 8; m; m >>= 1) gs += __shfl_xor_sync(0xffffffffu, gs, m);
        float gn = fmaxf(sqrtf(gs), EPSF);
        float xc = fminf(gn, 1.f - 1e-7f);
        float tt = xc / (1.f + sqrtf(1.f - xc * xc));  // tanh(0.5*atanh(xc))
        float f = beta * tt / gn;
        int qg = q0 + ty * 4 + j;
        #pragma unroll
        for (int i = 0; i < 4; i++)
            out[(size_t)qg * EM + h * HD + tx * 4 + i] = f * g[i];
    }
}

// ---------------- launch ----------------
extern "C" void kernel_launch(void* const* d_in, const int* in_sizes, int n_in,
                              void* d_out, int out_size) {
    const float* q  = (const float*)d_in[0];
    const float* k  = (const float*)d_in[1];
    const float* v  = (const float*)d_in[2];
    const float* Wq = (const float*)d_in[3];
    const float* Wk = (const float*)d_in[4];
    const float* Wv = (const float*)d_in[5];
    const float* bq = (const float*)d_in[6];
    const float* bk = (const float*)d_in[7];
    const float* bv = (const float*)d_in[8];
    const float* st = (const float*)d_in[9];
    const float* sg = (const float*)d_in[10];
    float* out = (float*)d_out;

    // beta(E/2,1/2) / beta(hd/2,1/2) via lgamma (host)
    double lb = (lgamma(256.0) + lgamma(0.5) - lgamma(256.5))
              - (lgamma(32.0) + lgamma(0.5) - lgamma(32.5));
    float beta = (float)exp(lb);

    cudaFuncSetAttribute(attn_k, cudaFuncAttributeMaxDynamicSharedMemorySize,
                         ATTN_SMEM_FLOATS * (int)sizeof(float));

    colnorm_k<<<dim3(2, 3), 256>>>(Wq, Wk, Wv, bq, bk, bv);
    rownorm_k<<<dim3(SQ, 3), 32>>>(q, k, v);
    proj_k<<<dim3(EM / 64, SQ / 64, 3), 256>>>(q, k, v, Wq, Wk, Wv);
    normaux_k<<<dim3(SQ, 3), 128>>>();
    transpose_k<<<dim3(EM / 32, SQ / 32, 2), dim3(32, 8)>>>();
    attn_k<<<(SQ / 64) * NH, 256, ATTN_SMEM_FLOATS * (int)sizeof(float)>>>(st, sg, beta, out);
    (void)in_sizes; (void)n_in; (void)out_size;
}